// round 1
// baseline (speedup 1.0000x reference)
#include <cuda_runtime.h>
#include <cstdint>

// VQExpert fused kernel, fp32 with packed fma.rn.f32x2.
// Pipeline per row: h = x@Wd^T+bd ; z = h@Wp^T+bp ; c* = argmin_c ||z - cb[c]||^2 ;
// v = cb[c*]@Wo^T+bo ; y = clamp(v@Wu^T+bu, -1, 1). Outputs: y [N*128], idx [N] (as f32), loss 0.

typedef unsigned long long ull;

#define FULLMASK 0xffffffffu

constexpr int NROW   = 500000;
constexpr int NTILES = NROW / 32;      // 15625, exact

// smem layout (floats)
constexpr int O_WD2 = 0;               // 128x128 k-pair interleaved: [(k>>1)*256 + j*2 + (k&1)]
constexpr int O_WU2 = 16384;
constexpr int O_WP2 = 32768;           // 32 cols:  [(k>>1)*64 + c*2 + (k&1)]
constexpr int O_WO2 = 36864;           // k=32:     [(k>>1)*256 + j*2 + (k&1)]
constexpr int O_CB  = 40960;           // codebook d-pair interleaved: [(d>>1)*512 + c*2 + (d&1)]
constexpr int O_CN  = 49152;           // 256 code norms
constexpr int O_BD  = 49408;
constexpr int O_BP  = 49536;
constexpr int O_BO  = 49568;
constexpr int O_BU  = 49696;
constexpr int O_TS  = 49824;           // 32 rows x 128, x -> h -> v (warp-private stripes)
constexpr int SMEM_FLOATS = 53920;
constexpr int SMEM_BYTES  = SMEM_FLOATS * 4;   // 215,680 B

__device__ __forceinline__ ull ffma2(ull a, ull b, ull c) {
    ull d;
    asm("fma.rn.f32x2 %0, %1, %2, %3;" : "=l"(d) : "l"(a), "l"(b), "l"(c));
    return d;
}
__device__ __forceinline__ ull packf2(float lo, float hi) {
    ull r;
    asm("mov.b64 %0, {%1, %2};" : "=l"(r) : "f"(lo), "f"(hi));
    return r;
}
__device__ __forceinline__ float f2sum(ull v) {
    float a, b;
    asm("mov.b64 {%0, %1}, %2;" : "=f"(a), "=f"(b) : "l"(v));
    return a + b;
}

__global__ void __launch_bounds__(256, 1)
vq_expert_kernel(const float* __restrict__ x,
                 const float* __restrict__ Wd, const float* __restrict__ bd,
                 const float* __restrict__ Wp, const float* __restrict__ bp,
                 const float* __restrict__ cb,
                 const float* __restrict__ Wo, const float* __restrict__ bo,
                 const float* __restrict__ Wu, const float* __restrict__ bu,
                 float* __restrict__ out)
{
    extern __shared__ float sm[];
    const int tid = threadIdx.x;

    // ---------------- stage weights (once per CTA) ----------------
    for (int i = tid; i < 128 * 128; i += 256) {
        int j = i >> 7, k = i & 127;
        int dst = (k >> 1) * 256 + j * 2 + (k & 1);
        sm[O_WD2 + dst] = Wd[i];
        sm[O_WU2 + dst] = Wu[i];
    }
    for (int i = tid; i < 4096; i += 256) {
        { int c = i >> 7, k = i & 127; sm[O_WP2 + (k >> 1) * 64 + c * 2 + (k & 1)] = Wp[i]; }
        { int j = i >> 5, k = i & 31;  sm[O_WO2 + (k >> 1) * 256 + j * 2 + (k & 1)] = Wo[i]; }
    }
    for (int i = tid; i < 256 * 32; i += 256) {
        int c = i >> 5, d = i & 31;
        sm[O_CB + (d >> 1) * 512 + c * 2 + (d & 1)] = cb[i];
    }
    {   // code norms ||c||^2 (the ||z||^2 term is row-constant -> dropped)
        float s = 0.f;
        #pragma unroll 8
        for (int d = 0; d < 32; d++) { float v = cb[tid * 32 + d]; s = fmaf(v, v, s); }
        sm[O_CN + tid] = s;
    }
    if (tid < 128) { sm[O_BD + tid] = bd[tid]; sm[O_BO + tid] = bo[tid]; sm[O_BU + tid] = bu[tid]; }
    if (tid < 32)  { sm[O_BP + tid] = bp[tid]; }
    if (blockIdx.x == 0 && tid == 0)
        out[(size_t)NROW * 128 + NROW] = 0.0f;    // commit_loss == 0 exactly
    __syncthreads();

    const int wid  = tid >> 5;
    const int lane = tid & 31;
    float* myts = sm + O_TS + wid * 512;          // this warp's 4 rows x 128

    const float4 bdv = ((const float4*)(sm + O_BD))[lane];
    const float4 bov = ((const float4*)(sm + O_BO))[lane];
    const float4 buv = ((const float4*)(sm + O_BU))[lane];
    const float  bpv = sm[O_BP + lane];
    float cn[8];
    #pragma unroll
    for (int i = 0; i < 8; i++) cn[i] = sm[O_CN + i * 32 + lane];

    float* outY = out;
    float* outI = out + (size_t)NROW * 128;

    for (int tile = blockIdx.x; tile < NTILES; tile += gridDim.x) {
        const int row0 = tile * 32 + wid * 4;

        // -------- stage x: 4 rows, coalesced float4 --------
        #pragma unroll
        for (int r = 0; r < 4; r++) {
            float4 v = ((const float4*)(x + (size_t)(row0 + r) * 128))[lane];
            ((float4*)(myts + r * 128))[lane] = v;
        }
        __syncwarp();

        // -------- phase A: h = x @ Wd^T (+bd), f32x2 over k-pairs --------
        ull acc[4][4];
        #pragma unroll
        for (int r = 0; r < 4; r++)
            #pragma unroll
            for (int t = 0; t < 4; t++) acc[r][t] = 0ull;

        #pragma unroll 8
        for (int p = 0; p < 64; p++) {
            const ulonglong2* wptr = (const ulonglong2*)(sm + O_WD2 + p * 256 + 8 * lane);
            ulonglong2 wa = wptr[0], wb = wptr[1];   // cols 4*lane .. 4*lane+3
            #pragma unroll
            for (int r = 0; r < 4; r++) {
                ull x2 = *(const ull*)(myts + r * 128 + 2 * p);
                acc[r][0] = ffma2(x2, wa.x, acc[r][0]);
                acc[r][1] = ffma2(x2, wa.y, acc[r][1]);
                acc[r][2] = ffma2(x2, wb.x, acc[r][2]);
                acc[r][3] = ffma2(x2, wb.y, acc[r][3]);
            }
        }
        __syncwarp();
        #pragma unroll
        for (int r = 0; r < 4; r++) {
            float4 h;
            h.x = bdv.x + f2sum(acc[r][0]);
            h.y = bdv.y + f2sum(acc[r][1]);
            h.z = bdv.z + f2sum(acc[r][2]);
            h.w = bdv.w + f2sum(acc[r][3]);
            ((float4*)(myts + r * 128))[lane] = h;   // ts now holds h
        }
        __syncwarp();

        // -------- phase B: z = h @ Wp^T (+bp), lane = z-column --------
        ull za[4] = {0ull, 0ull, 0ull, 0ull};
        #pragma unroll 8
        for (int k2 = 0; k2 < 64; k2++) {
            ull w2 = *(const ull*)(sm + O_WP2 + k2 * 64 + 2 * lane);
            #pragma unroll
            for (int r = 0; r < 4; r++) {
                ull h2 = *(const ull*)(myts + r * 128 + 2 * k2);
                za[r] = ffma2(h2, w2, za[r]);
            }
        }
        float zv[4];
        #pragma unroll
        for (int r = 0; r < 4; r++) zv[r] = bpv + f2sum(za[r]);

        // -------- phase C: z . cb[c] for 256 codes, argmin of ||c||^2 - 2 z.c --------
        ull da[4][8];
        #pragma unroll
        for (int r = 0; r < 4; r++)
            #pragma unroll
            for (int i = 0; i < 8; i++) da[r][i] = 0ull;

        #pragma unroll 2
        for (int d2 = 0; d2 < 16; d2++) {
            ull z2[4];
            #pragma unroll
            for (int r = 0; r < 4; r++) {
                float zl = __shfl_sync(FULLMASK, zv[r], 2 * d2);
                float zh = __shfl_sync(FULLMASK, zv[r], 2 * d2 + 1);
                z2[r] = packf2(zl, zh);
            }
            #pragma unroll
            for (int i = 0; i < 8; i++) {
                ull c2 = *(const ull*)(sm + O_CB + d2 * 512 + (i * 32 + lane) * 2);
                #pragma unroll
                for (int r = 0; r < 4; r++) da[r][i] = ffma2(z2[r], c2, da[r][i]);
            }
        }
        int bc[4];
        #pragma unroll
        for (int r = 0; r < 4; r++) {
            float bs = 3.4e38f; int bi = 0;
            #pragma unroll
            for (int i = 0; i < 8; i++) {
                float s = cn[i] - 2.0f * f2sum(da[r][i]);
                int c = (i << 5) | lane;
                if (s < bs) { bs = s; bi = c; }
            }
            #pragma unroll
            for (int off = 16; off > 0; off >>= 1) {
                float s2 = __shfl_xor_sync(FULLMASK, bs, off);
                int   c2 = __shfl_xor_sync(FULLMASK, bi, off);
                if (s2 < bs || (s2 == bs && c2 < bi)) { bs = s2; bi = c2; }
            }
            bc[r] = bi;   // warp-uniform
        }

        // -------- phase D: v = cb[bc] @ Wo^T (+bo) --------
        ull va[4][4];
        #pragma unroll
        for (int r = 0; r < 4; r++)
            #pragma unroll
            for (int t = 0; t < 4; t++) va[r][t] = 0ull;

        #pragma unroll 4
        for (int k2 = 0; k2 < 16; k2++) {
            const ulonglong2* wptr = (const ulonglong2*)(sm + O_WO2 + k2 * 256 + 8 * lane);
            ulonglong2 wa = wptr[0], wb = wptr[1];
            #pragma unroll
            for (int r = 0; r < 4; r++) {
                ull q2 = *(const ull*)(sm + O_CB + k2 * 512 + bc[r] * 2);
                va[r][0] = ffma2(q2, wa.x, va[r][0]);
                va[r][1] = ffma2(q2, wa.y, va[r][1]);
                va[r][2] = ffma2(q2, wb.x, va[r][2]);
                va[r][3] = ffma2(q2, wb.y, va[r][3]);
            }
        }
        __syncwarp();
        #pragma unroll
        for (int r = 0; r < 4; r++) {
            float4 v;
            v.x = bov.x + f2sum(va[r][0]);
            v.y = bov.y + f2sum(va[r][1]);
            v.z = bov.z + f2sum(va[r][2]);
            v.w = bov.w + f2sum(va[r][3]);
            ((float4*)(myts + r * 128))[lane] = v;   // ts now holds v
        }
        __syncwarp();

        // -------- phase E: y = clamp(v @ Wu^T + bu) --------
        ull ea[4][4];
        #pragma unroll
        for (int r = 0; r < 4; r++)
            #pragma unroll
            for (int t = 0; t < 4; t++) ea[r][t] = 0ull;

        #pragma unroll 8
        for (int p = 0; p < 64; p++) {
            const ulonglong2* wptr = (const ulonglong2*)(sm + O_WU2 + p * 256 + 8 * lane);
            ulonglong2 wa = wptr[0], wb = wptr[1];
            #pragma unroll
            for (int r = 0; r < 4; r++) {
                ull v2 = *(const ull*)(myts + r * 128 + 2 * p);
                ea[r][0] = ffma2(v2, wa.x, ea[r][0]);
                ea[r][1] = ffma2(v2, wa.y, ea[r][1]);
                ea[r][2] = ffma2(v2, wb.x, ea[r][2]);
                ea[r][3] = ffma2(v2, wb.y, ea[r][3]);
            }
        }
        #pragma unroll
        for (int r = 0; r < 4; r++) {
            float4 y;
            y.x = fminf(fmaxf(buv.x + f2sum(ea[r][0]), -1.0f), 1.0f);
            y.y = fminf(fmaxf(buv.y + f2sum(ea[r][1]), -1.0f), 1.0f);
            y.z = fminf(fmaxf(buv.z + f2sum(ea[r][2]), -1.0f), 1.0f);
            y.w = fminf(fmaxf(buv.w + f2sum(ea[r][3]), -1.0f), 1.0f);
            ((float4*)(outY + (size_t)(row0 + r) * 128))[lane] = y;
        }
        if (lane == 0) {
            #pragma unroll
            for (int r = 0; r < 4; r++) outI[row0 + r] = (float)bc[r];
        }
        __syncwarp();
    }
}

extern "C" void kernel_launch(void* const* d_in, const int* in_sizes, int n_in,
                              void* d_out, int out_size)
{
    const float* x  = (const float*)d_in[0];
    const float* Wd = (const float*)d_in[1];
    const float* bd = (const float*)d_in[2];
    const float* Wp = (const float*)d_in[3];
    const float* bp = (const float*)d_in[4];
    const float* cb = (const float*)d_in[5];
    const float* Wo = (const float*)d_in[6];
    const float* bo = (const float*)d_in[7];
    const float* Wu = (const float*)d_in[8];
    const float* bu = (const float*)d_in[9];
    float* out = (float*)d_out;

    cudaFuncSetAttribute(vq_expert_kernel,
                         cudaFuncAttributeMaxDynamicSharedMemorySize, SMEM_BYTES);

    vq_expert_kernel<<<148, 256, SMEM_BYTES>>>(x, Wd, bd, Wp, bp, cb, Wo, bo, Wu, bu, out);
}